// round 16
// baseline (speedup 1.0000x reference)
#include <cuda_runtime.h>
#include <math.h>

#define BB 16
#define NN 2000
#define CC 81
#define NPAD 2048
#define MAXC 64
#define MAXI 100
#define MIN_CONF 0.7f
#define NMS_TH 0.3f
#define FULL 0xffffffffu
#define RGRID 148
#define KLCAP 2048

typedef unsigned long long ull;

// Scratch (static device globals — no runtime allocation).
// Zero-init invariants: g_cnt reset by NMS each run; g_ndone/g_nkept reset by
// k_classify block 0 each run (kernel-boundary ordered before k_rest).
__device__ float4         g_bx[BB * NPAD];
__device__ float          g_sc[BB * NPAD];
__device__ int            g_cl[BB * NPAD];
__device__ int            g_cnt[BB * 80];
__device__ ull            g_skey[BB * 80 * MAXC];   // (score<<32)|((2047-n)<<6)|pos
__device__ float4         g_sbox[BB * 80 * MAXC];   // refined box per slot
__device__ int            g_ndone[BB];              // NMS tasks done per batch (80)
__device__ int            g_nkept[BB];              // kept count per batch
__device__ ull            g_klist[BB * KLCAP];      // kept keys: (score<<32)|(0xFFFF-n)

// ---------------------------------------------------------------------------
// K1: one warp per 4 ROIs (8000 warps), unrolled float4 loads. Float-compare
// argmax tracking (pack to u64 only at the end); per-ROI keys combine via 4
// per-warp shared u64 atomicMax slots; 4 lanes run refine tails and write the
// NMS inputs (key + box) directly into per-class slots.
// ---------------------------------------------------------------------------
__global__ void __launch_bounds__(256) k_classify(const float* __restrict__ rois,
                                                  const float* __restrict__ probs,
                                                  const float* __restrict__ deltas) {
    __shared__ ull allslots[8][4];            // [warp][roi]
    int w    = threadIdx.x >> 5;
    int lane = threadIdx.x & 31;
    int task = blockIdx.x * 8 + w;

    if (blockIdx.x == 0) {
        if (threadIdx.x < BB)                         g_ndone[threadIdx.x] = 0;
        else if (threadIdx.x < 2 * BB)                g_nkept[threadIdx.x - BB] = 0;
    }

    if (task >= (BB * NN) / 4) return;

    ull* slots = allslots[w];
    if (lane < 4) slots[lane] = 0;
    __syncwarp();

    float4 myroi = make_float4(0.f, 0.f, 0.f, 0.f);
    if (lane < 4) myroi = __ldg((const float4*)rois + (task * 4 + lane));

    const float4* pq = (const float4*)(probs + (size_t)task * 324);
    int q0 = (81 * lane) >> 5;
    int q1 = (81 * (lane + 1)) >> 5;          // q1-q0 in {2,3}
    int p   = q0 * 4;
    int roi = p / 81;
    int c   = p - roi * 81;
    float bvA = -1.0f, bvB = -1.0f;
    int   bcA = 0,     bcB = 0;
    int   roiA = roi,  roiB = -1;

    // strict > keeps lowest class per segment (ascending c) -> jnp.argmax tie
#define PROC_F(f) {                                                 \
    if (roi == roiA) { if ((f) > bvA) { bvA = (f); bcA = c; } }     \
    else             { roiB = roi; if ((f) > bvB) { bvB = (f); bcB = c; } } \
    if (++c == 81) { c = 0; ++roi; } }

#pragma unroll
    for (int u = 0; u < 3; u++) {
        bool act = (u < 2) | (q0 + u < q1);
        if (act) {
            float4 v = __ldg(pq + q0 + u);
            PROC_F(v.x) PROC_F(v.y) PROC_F(v.z) PROC_F(v.w)
        }
    }
#undef PROC_F
    // probs >= 0 -> float bits monotone unsigned; 255-c resolves cross-lane
    // ties to the lowest class index under unsigned max.
    ull keyA = ((ull)__float_as_uint(bvA) << 32) | (unsigned)(255 - bcA);
    atomicMax(slots + roiA, keyA);
    if (roiB >= 0) {
        ull keyB = ((ull)__float_as_uint(bvB) << 32) | (unsigned)(255 - bcB);
        atomicMax(slots + roiB, keyB);
    }
    __syncwarp();

    if (lane < 4) {
        ull  key = slots[lane];
        int   bi = 255 - (int)(key & 0xFFull);
        float sv = __uint_as_float((unsigned)(key >> 32));
        int   g  = task * 4 + lane;

        float4 d = __ldg((const float4*)deltas + ((size_t)g * CC + bi));
        float h  = myroi.z - myroi.x;
        float ww = myroi.w - myroi.y;
        float cy = myroi.x + 0.5f * h;
        float cx = myroi.y + 0.5f * ww;
        cy += d.x * 0.1f * h;
        cx += d.y * 0.1f * ww;
        h  *= expf(d.z * 0.2f);
        ww *= expf(d.w * 0.2f);
        float y1 = fminf(fmaxf(cy - 0.5f * h,  0.f), 1.f);
        float x1 = fminf(fmaxf(cx - 0.5f * ww, 0.f), 1.f);
        float y2 = fminf(fmaxf(cy + 0.5f * h,  0.f), 1.f);
        float x2 = fminf(fmaxf(cx + 0.5f * ww, 0.f), 1.f);

        bool valid = (bi > 0) && (sv >= MIN_CONF);
        int  b = g / NN;
        int  n = g - b * NN;
        int  o = b * NPAD + n;
        float4 box = make_float4(y1, x1, y2, x2);
        g_bx[o] = box;
        g_cl[o] = bi;
        g_sc[o] = valid ? sv : -1.0f;
        if (valid) {
            int cidx = b * 80 + (bi - 1);
            int pos  = atomicAdd(&g_cnt[cidx], 1);
            if (pos < MAXC) {
                // key: score desc, then smaller n (stable argsort), pos in low 6
                g_skey[cidx * MAXC + pos] =
                    ((ull)__float_as_uint(sv) << 32) |
                    ((unsigned)(2047 - n) << 6) | (unsigned)pos;
                g_sbox[cidx * MAXC + pos] = box;
            }
        }
    }
}

// ---------------------------------------------------------------------------
// Warp-register bitonic sorts, descending. Pads (key 0) sink to the end.
// ---------------------------------------------------------------------------
__device__ __forceinline__ void bsort32(ull& k0, int lane) {
#pragma unroll
    for (int kk = 2; kk <= 32; kk <<= 1) {
#pragma unroll
        for (int d = kk >> 1; d > 0; d >>= 1) {
            ull o = __shfl_xor_sync(FULL, k0, d);
            bool lower = ((lane & d) == 0);
            bool asc   = ((lane & kk) == 0);
            k0 = (asc == lower) ? (k0 > o ? k0 : o) : (k0 > o ? o : k0);
        }
    }
}

__device__ __forceinline__ void bsort64(ull& k0, ull& k1, int lane) {
#pragma unroll
    for (int kk = 2; kk <= 64; kk <<= 1) {
#pragma unroll
        for (int d = kk >> 1; d > 0; d >>= 1) {
            if (d == 32) {
                ull mx = k0 > k1 ? k0 : k1;
                ull mn = k0 > k1 ? k1 : k0;
                k0 = mx; k1 = mn;
            } else {
                ull o0 = __shfl_xor_sync(FULL, k0, d);
                ull o1 = __shfl_xor_sync(FULL, k1, d);
                bool lower = ((lane & d) == 0);
                bool asc0  = ((lane & kk) == 0);
                bool asc1  = (((lane + 32) & kk) == 0);
                k0 = (asc0 == lower) ? (k0 > o0 ? k0 : o0) : (k0 > o0 ? o0 : k0);
                k1 = (asc1 == lower) ? (k1 > o1 ? k1 : o1) : (k1 > o1 ? o1 : k1);
            }
        }
    }
}

// ---------------------------------------------------------------------------
// K2 (persistent, 148 blocks): NMS full-chip (colocated key+box inputs, kept
// keys appended to per-batch compact lists), then ALL blocks run select
// redundantly (bid%16) from the compact lists.
// ---------------------------------------------------------------------------
__global__ void __launch_bounds__(1024, 1)
k_rest(float* __restrict__ out) {
    // smem: NMS sbox[9][64] float4 [0,9216) + sar [9216,11520)
    //       select hist[2048] int [0,8192) + cand[256] ull [8192,10240)
    //              + srow[600] float [10240,12640)
    __shared__ __align__(16) unsigned char sraw[12640];
    __shared__ int s_ncand;
    __shared__ int s_bstar;

    int bid  = blockIdx.x;
    int t    = threadIdx.x;
    int w    = t >> 5;
    int lane = t & 31;

    // ================= Phase A: per-class NMS, full-chip spread =============
    // task = w*RGRID + bid (warps 0..8 in every block; 1280 tasks).
    // Cross-class IoU is exactly 0 (class offset 2 on clipped [0,1] boxes),
    // so per-class greedy == reference global greedy NMS.
    {
        float4* sbox = (float4*)(sraw);                  // [9][64]
        float*  sar  = (float*) (sraw + 9216);           // [9][64]
        int gw = w * RGRID + bid;
        if (gw < BB * 80) {
            int b  = gw / 80;
            int cnt = min(g_cnt[gw], MAXC);

            // one coalesced round trip: keys + boxes together
            ull    k0 = 0, k1 = 0;
            float4 P0 = make_float4(0.f, 0.f, 0.f, 0.f);
            float4 P1 = make_float4(0.f, 0.f, 0.f, 0.f);
            if (lane < cnt)      { k0 = g_skey[gw * MAXC + lane];      P0 = g_sbox[gw * MAXC + lane]; }
            if (lane + 32 < cnt) { k1 = g_skey[gw * MAXC + lane + 32]; P1 = g_sbox[gw * MAXC + lane + 32]; }

            // stage boxes by slot position (pre-sort)
            sbox[w * MAXC + lane]      = P0;
            sbox[w * MAXC + lane + 32] = P1;
            __syncwarp();

            if (cnt <= 32) bsort32(k0, lane);
            else           bsort64(k0, k1, lane);

            bool v0 = (lane < cnt);
            bool v1 = (lane + 32 < cnt);
            int  p0 = (int)(k0 & 63ull);
            int  p1 = (int)(k1 & 63ull);
            float4 B0 = sbox[w * MAXC + p0];     // permute boxes via smem
            float4 B1 = sbox[w * MAXC + p1];
            __syncwarp();                        // all reads before overwrite
            float a0 = (B0.z - B0.x) * (B0.w - B0.y);
            float a1 = (B1.z - B1.x) * (B1.w - B1.y);
            sbox[w * MAXC + lane]      = B0;  sar[w * MAXC + lane]      = a0;
            sbox[w * MAXC + lane + 32] = B1;  sar[w * MAXC + lane + 32] = a1;
            __syncwarp();

            // forward masks: f bit j set iff j > e and IoU(e,j) > thresh
            ull f0 = 0, f1 = 0;
#pragma unroll 4
            for (int j = 0; j < cnt; j++) {
                float4 bj = sbox[w * MAXC + j];
                float  aj = sar [w * MAXC + j];
                if (v0 && j > lane) {
                    float ih = fmaxf(fminf(B0.z, bj.z) - fmaxf(B0.x, bj.x), 0.f);
                    float iw = fmaxf(fminf(B0.w, bj.w) - fmaxf(B0.y, bj.y), 0.f);
                    float inter = ih * iw;
                    if (inter > NMS_TH * fmaxf(a0 + aj - inter, 1e-8f)) f0 |= 1ull << j;
                }
                if (v1 && j > lane + 32) {
                    float ih = fmaxf(fminf(B1.z, bj.z) - fmaxf(B1.x, bj.x), 0.f);
                    float iw = fmaxf(fminf(B1.w, bj.w) - fmaxf(B1.y, bj.y), 0.f);
                    float inter = ih * iw;
                    if (inter > NMS_TH * fmaxf(a1 + aj - inter, 1e-8f)) f1 |= 1ull << j;
                }
            }

            // greedy: take best alive, keep it, kill whom it suppresses.
            ull alive = (cnt >= 64) ? ~0ull : ((1ull << cnt) - 1ull);
            ull kept  = 0;
            while (alive) {
                int i = __ffsll((long long)alive) - 1;
                kept |= 1ull << i;
                ull fi = __shfl_sync(FULL, (i >= 32) ? f1 : f0, i & 31);
                alive &= ~fi;
                alive &= ~(1ull << i);
            }

            // append kept keys (score | 0xFFFF-n) to the batch's compact list
            if (v0 && ((kept >> lane) & 1ull)) {
                int n0 = 2047 - (int)((k0 >> 6) & 0x7FFull);
                int pos = atomicAdd(&g_nkept[b], 1);
                if (pos < KLCAP)
                    g_klist[b * KLCAP + pos] = (k0 & 0xFFFFFFFF00000000ull) | (unsigned)(0xFFFF - n0);
            }
            if (v1 && ((kept >> (lane + 32)) & 1ull)) {
                int n1 = 2047 - (int)((k1 >> 6) & 0x7FFull);
                int pos = atomicAdd(&g_nkept[b], 1);
                if (pos < KLCAP)
                    g_klist[b * KLCAP + pos] = (k1 & 0xFFFFFFFF00000000ull) | (unsigned)(0xFFFF - n1);
            }
            if (lane == 0) g_cnt[gw] = 0;   // restore zero-invariant

            // release: klist writes visible, then signal this batch
            __threadfence();
            __syncwarp();
            if (lane == 0) atomicAdd(&g_ndone[b], 1);
        }
    }

    __syncthreads();   // NMS warps done with sraw before reuse

    // ================= Phase B: redundant select (all 148 blocks) ===========
    {
        int*   hist = (int*)sraw;                // [2048]
        ull*   cand = (ull*)(sraw + 8192);       // [256]
        float* srow = (float*)(sraw + 10240);    // [600]
        int    b    = bid & 15;
        int    gb   = b * NPAD;
        float* ob   = out + b * (MAXI * 6);

        for (int i = t; i < 2048; i += 1024) hist[i] = 0;
        for (int i = t; i < MAXI * 6; i += 1024) srow[i] = 0.0f;
        if (t == 0) { s_ncand = 0; s_bstar = 0; }

        // wait until this batch's 80 NMS tasks are done (single poller).
        // g_ndone/g_nkept are reset by the NEXT run's k_classify, so late
        // redundant pollers can never miss the signal.
        if (t == 0) {
            while (*(volatile int*)&g_ndone[b] < 80) { }
        }
        __syncthreads();
        __threadfence();   // acquire

        int mk = min(g_nkept[b], KLCAP);

        // load this thread's keys (coalesced; mk ~ 960 expected, <= 2048)
        ull myk0 = (t < mk)        ? g_klist[b * KLCAP + t]        : 0;
        ull myk1 = (t + 1024 < mk) ? g_klist[b * KLCAP + t + 1024] : 0;

        // histogram on score bits; kept => score in (0.7,1) -> bucket [819,2047]
        if (myk0) {
            int bk = (int)(((unsigned)(myk0 >> 32) - 0x3F000000u) >> 12);
            atomicAdd(&hist[min(2047, max(0, bk))], 1);
        }
        if (myk1) {
            int bk = (int)(((unsigned)(myk1 >> 32) - 0x3F000000u) >> 12);
            atomicAdd(&hist[min(2047, max(0, bk))], 1);
        }
        __syncthreads();

        // two-level suffix scan: thread t covers buckets {2t, 2t+1};
        // find b* = max bucket with suffix count >= 100 (unique transition)
        {
            __shared__ int wsum[32];
            __shared__ int wsuf[32];
            int h0  = hist[2 * t];
            int h1  = hist[2 * t + 1];
            int loc = h0 + h1;
            int suf = loc;
            for (int d = 1; d < 32; d <<= 1) {
                int v = __shfl_down_sync(FULL, suf, d);
                if (lane + d < 32) suf += v;
            }
            if (lane == 0) wsum[w] = suf;
            __syncthreads();
            if (t == 0) {
                int acc = 0;
                for (int w2 = 31; w2 >= 0; w2--) { wsuf[w2] = acc; acc += wsum[w2]; }
            }
            __syncthreads();
            int run = wsuf[w] + (suf - loc);
            int S = run + h1;
            if (S >= MAXI && run < MAXI) s_bstar = 2 * t + 1;
            run = S;
            S = run + h0;
            if (S >= MAXI && run < MAXI) s_bstar = 2 * t;
        }
        __syncthreads();

        unsigned tbits = 0x3F000000u + ((unsigned)s_bstar << 12);
        if (myk0 && (unsigned)(myk0 >> 32) >= tbits) {
            int p = atomicAdd(&s_ncand, 1);
            if (p < 256) cand[p] = myk0;
        }
        if (myk1 && (unsigned)(myk1 >> 32) >= tbits) {
            int p = atomicAdd(&s_ncand, 1);
            if (p < 256) cand[p] = myk1;
        }
        __syncthreads();

        // rank-based emit into shared staging: thread t handles candidate t;
        // rank = number of strictly greater keys (keys distinct, order-free).
        int m = min(s_ncand, 256);
        if (t < m) {
            ull my = cand[t];
            int rank = 0;
            for (int j = 0; j < m; j++) rank += (cand[j] > my);
            if (rank < MAXI) {
                int idx = 0xFFFF - (int)(my & 0xFFFFull);
                float sc = __uint_as_float((unsigned)(my >> 32));
                float4 bx = g_bx[gb + idx];
                float* row = srow + rank * 6;
                row[0] = bx.x; row[1] = bx.y; row[2] = bx.z; row[3] = bx.w;
                row[4] = (float)g_cl[gb + idx]; row[5] = sc;
            }
        }
        __syncthreads();

        // every redundant block writes the IDENTICAL 600-float image
        for (int i = t; i < MAXI * 6; i += 1024) ob[i] = srow[i];
    }
}

// ---------------------------------------------------------------------------
extern "C" void kernel_launch(void* const* d_in, const int* in_sizes, int n_in,
                              void* d_out, int out_size) {
    const float* rois   = nullptr;
    const float* probs  = nullptr;
    const float* deltas = nullptr;
    for (int i = 0; i < n_in; i++) {
        if      (in_sizes[i] == BB * NN * 4)      rois   = (const float*)d_in[i];
        else if (in_sizes[i] == BB * NN * CC)     probs  = (const float*)d_in[i];
        else if (in_sizes[i] == BB * NN * CC * 4) deltas = (const float*)d_in[i];
    }
    float* out = (float*)d_out;

    k_classify<<<BB * NN / 4 / 8, 256>>>(rois, probs, deltas); // 4 ROIs/warp
    k_rest    <<<RGRID, 1024>>>(out);                          // NMS + select
}

// round 17
// speedup vs baseline: 1.5679x; 1.5679x over previous
#include <cuda_runtime.h>
#include <math.h>

#define BB 16
#define NN 2000
#define CC 81
#define MAXC 64
#define MAXI 100
#define MIN_CONF 0.7f
#define NMS_TH 0.3f
#define FULL 0xffffffffu
#define RGRID 148
#define KLCAP 4096

typedef unsigned long long ull;

// Scratch (static device globals — no runtime allocation).
// Zero-init invariants: g_cnt reset by NMS each run; g_ndone/g_nkept reset by
// k_classify block 0 each run (kernel-boundary ordered before k_rest).
// Key layout: (score<<32) | (2047-n)<<13 | class0<<6 | pos
//   -> unsigned compare == (score desc, n asc) == stable argsort(-scores).
__device__ int            g_cnt[BB * 80];
__device__ ull            g_skey[BB * 80 * MAXC];
__device__ float4         g_sbox[BB * 80 * MAXC];
__device__ int            g_ndone[BB];              // NMS tasks done per batch (80)
__device__ int            g_nkept[BB];              // kept count per batch
__device__ ull            g_klist[BB * KLCAP];      // kept keys, compact per batch

// ---------------------------------------------------------------------------
// K1: one warp per 4 ROIs (8000 warps), unrolled float4 loads. Float-compare
// argmax per segment, per-ROI keys combine via 4 per-warp shared u64
// atomicMax slots; 4 lanes run refine tails and write key+box into per-class
// slots (the ONLY outputs — no separate box/class/score arrays).
// ---------------------------------------------------------------------------
__global__ void __launch_bounds__(256) k_classify(const float* __restrict__ rois,
                                                  const float* __restrict__ probs,
                                                  const float* __restrict__ deltas) {
    __shared__ ull allslots[8][4];            // [warp][roi]
    int w    = threadIdx.x >> 5;
    int lane = threadIdx.x & 31;
    int task = blockIdx.x * 8 + w;

    if (blockIdx.x == 0) {
        if (threadIdx.x < BB)          g_ndone[threadIdx.x] = 0;
        else if (threadIdx.x < 2 * BB) g_nkept[threadIdx.x - BB] = 0;
    }

    if (task >= (BB * NN) / 4) return;

    ull* slots = allslots[w];
    if (lane < 4) slots[lane] = 0;
    __syncwarp();

    float4 myroi = make_float4(0.f, 0.f, 0.f, 0.f);
    if (lane < 4) myroi = __ldg((const float4*)rois + (task * 4 + lane));

    const float4* pq = (const float4*)(probs + (size_t)task * 324);
    int q0 = (81 * lane) >> 5;
    int q1 = (81 * (lane + 1)) >> 5;          // q1-q0 in {2,3}
    int p   = q0 * 4;
    int roi = p / 81;
    int c   = p - roi * 81;
    float bvA = -1.0f, bvB = -1.0f;
    int   bcA = 0,     bcB = 0;
    int   roiA = roi,  roiB = -1;

    // strict > keeps lowest class per segment (ascending c) -> jnp.argmax tie
#define PROC_F(f) {                                                 \
    if (roi == roiA) { if ((f) > bvA) { bvA = (f); bcA = c; } }     \
    else             { roiB = roi; if ((f) > bvB) { bvB = (f); bcB = c; } } \
    if (++c == 81) { c = 0; ++roi; } }

#pragma unroll
    for (int u = 0; u < 3; u++) {
        bool act = (u < 2) | (q0 + u < q1);
        if (act) {
            float4 v = __ldg(pq + q0 + u);
            PROC_F(v.x) PROC_F(v.y) PROC_F(v.z) PROC_F(v.w)
        }
    }
#undef PROC_F
    // probs >= 0 -> float bits monotone unsigned; 255-c resolves cross-lane
    // ties to the lowest class index under unsigned max.
    ull keyA = ((ull)__float_as_uint(bvA) << 32) | (unsigned)(255 - bcA);
    atomicMax(slots + roiA, keyA);
    if (roiB >= 0) {
        ull keyB = ((ull)__float_as_uint(bvB) << 32) | (unsigned)(255 - bcB);
        atomicMax(slots + roiB, keyB);
    }
    __syncwarp();

    if (lane < 4) {
        ull  key = slots[lane];
        int   bi = 255 - (int)(key & 0xFFull);
        float sv = __uint_as_float((unsigned)(key >> 32));
        int   g  = task * 4 + lane;

        bool valid = (bi > 0) && (sv >= MIN_CONF);
        if (valid) {
            float4 d = __ldg((const float4*)deltas + ((size_t)g * CC + bi));
            float h  = myroi.z - myroi.x;
            float ww = myroi.w - myroi.y;
            float cy = myroi.x + 0.5f * h;
            float cx = myroi.y + 0.5f * ww;
            cy += d.x * 0.1f * h;
            cx += d.y * 0.1f * ww;
            h  *= expf(d.z * 0.2f);
            ww *= expf(d.w * 0.2f);
            float y1 = fminf(fmaxf(cy - 0.5f * h,  0.f), 1.f);
            float x1 = fminf(fmaxf(cx - 0.5f * ww, 0.f), 1.f);
            float y2 = fminf(fmaxf(cy + 0.5f * h,  0.f), 1.f);
            float x2 = fminf(fmaxf(cx + 0.5f * ww, 0.f), 1.f);

            int b  = g / NN;
            int n  = g - b * NN;
            int c0 = bi - 1;                       // 0..79
            int cidx = b * 80 + c0;
            int pos  = atomicAdd(&g_cnt[cidx], 1);
            if (pos < MAXC) {
                g_skey[cidx * MAXC + pos] =
                    ((ull)__float_as_uint(sv) << 32) |
                    ((ull)(unsigned)(2047 - n) << 13) |
                    ((unsigned)c0 << 6) | (unsigned)pos;
                g_sbox[cidx * MAXC + pos] = make_float4(y1, x1, y2, x2);
            }
        }
    }
}

// ---------------------------------------------------------------------------
// Warp-register bitonic sorts, descending. Pads (key 0) sink to the end.
// ---------------------------------------------------------------------------
__device__ __forceinline__ void bsort32(ull& k0, int lane) {
#pragma unroll
    for (int kk = 2; kk <= 32; kk <<= 1) {
#pragma unroll
        for (int d = kk >> 1; d > 0; d >>= 1) {
            ull o = __shfl_xor_sync(FULL, k0, d);
            bool lower = ((lane & d) == 0);
            bool asc   = ((lane & kk) == 0);
            k0 = (asc == lower) ? (k0 > o ? k0 : o) : (k0 > o ? o : k0);
        }
    }
}

__device__ __forceinline__ void bsort64(ull& k0, ull& k1, int lane) {
#pragma unroll
    for (int kk = 2; kk <= 64; kk <<= 1) {
#pragma unroll
        for (int d = kk >> 1; d > 0; d >>= 1) {
            if (d == 32) {
                ull mx = k0 > k1 ? k0 : k1;
                ull mn = k0 > k1 ? k1 : k0;
                k0 = mx; k1 = mn;
            } else {
                ull o0 = __shfl_xor_sync(FULL, k0, d);
                ull o1 = __shfl_xor_sync(FULL, k1, d);
                bool lower = ((lane & d) == 0);
                bool asc0  = ((lane & kk) == 0);
                bool asc1  = (((lane + 32) & kk) == 0);
                k0 = (asc0 == lower) ? (k0 > o0 ? k0 : o0) : (k0 > o0 ? o0 : k0);
                k1 = (asc1 == lower) ? (k1 > o1 ? k1 : o1) : (k1 > o1 ? o1 : k1);
            }
        }
    }
}

// ---------------------------------------------------------------------------
// K2 (persistent, 148 blocks): NMS full-chip with colocated key+box inputs;
// kept keys appended to per-batch compact lists via WARP-AGGREGATED atomics
// (one atomicAdd per class-warp, not per kept box). Then all blocks run
// select redundantly (bid%16) from the compact lists.
// ---------------------------------------------------------------------------
__global__ void __launch_bounds__(1024, 1)
k_rest(float* __restrict__ out) {
    // smem: NMS sbox[9][64] float4 [0,9216) + sar [9216,11520)
    //       select hist[2048] int [0,8192) + cand[256] ull [8192,10240)
    //              + srow[600] float [10240,12640)
    __shared__ __align__(16) unsigned char sraw[12640];
    __shared__ int s_ncand;
    __shared__ int s_bstar;

    int bid  = blockIdx.x;
    int t    = threadIdx.x;
    int w    = t >> 5;
    int lane = t & 31;

    // ================= Phase A: per-class NMS, full-chip spread =============
    // task = w*RGRID + bid (warps 0..8 in every block; 1280 tasks).
    // Cross-class IoU is exactly 0 (class offset 2 on clipped [0,1] boxes),
    // so per-class greedy == reference global greedy NMS.
    {
        float4* sbox = (float4*)(sraw);                  // [9][64]
        float*  sar  = (float*) (sraw + 9216);           // [9][64]
        int gw = w * RGRID + bid;
        if (gw < BB * 80) {
            int b  = gw / 80;
            int cnt = min(g_cnt[gw], MAXC);

            // one coalesced round trip: keys + boxes together
            ull    k0 = 0, k1 = 0;
            float4 P0 = make_float4(0.f, 0.f, 0.f, 0.f);
            float4 P1 = make_float4(0.f, 0.f, 0.f, 0.f);
            if (lane < cnt)      { k0 = g_skey[gw * MAXC + lane];      P0 = g_sbox[gw * MAXC + lane]; }
            if (lane + 32 < cnt) { k1 = g_skey[gw * MAXC + lane + 32]; P1 = g_sbox[gw * MAXC + lane + 32]; }

            // stage boxes by slot position (pre-sort)
            sbox[w * MAXC + lane]      = P0;
            sbox[w * MAXC + lane + 32] = P1;
            __syncwarp();

            if (cnt <= 32) bsort32(k0, lane);
            else           bsort64(k0, k1, lane);

            bool v0 = (lane < cnt);
            bool v1 = (lane + 32 < cnt);
            int  p0 = (int)(k0 & 63ull);
            int  p1 = (int)(k1 & 63ull);
            float4 B0 = sbox[w * MAXC + p0];     // permute boxes via smem
            float4 B1 = sbox[w * MAXC + p1];
            __syncwarp();                        // all reads before overwrite
            float a0 = (B0.z - B0.x) * (B0.w - B0.y);
            float a1 = (B1.z - B1.x) * (B1.w - B1.y);
            sbox[w * MAXC + lane]      = B0;  sar[w * MAXC + lane]      = a0;
            sbox[w * MAXC + lane + 32] = B1;  sar[w * MAXC + lane + 32] = a1;
            __syncwarp();

            // forward masks: f bit j set iff j > e and IoU(e,j) > thresh
            ull f0 = 0, f1 = 0;
#pragma unroll 4
            for (int j = 0; j < cnt; j++) {
                float4 bj = sbox[w * MAXC + j];
                float  aj = sar [w * MAXC + j];
                if (v0 && j > lane) {
                    float ih = fmaxf(fminf(B0.z, bj.z) - fmaxf(B0.x, bj.x), 0.f);
                    float iw = fmaxf(fminf(B0.w, bj.w) - fmaxf(B0.y, bj.y), 0.f);
                    float inter = ih * iw;
                    if (inter > NMS_TH * fmaxf(a0 + aj - inter, 1e-8f)) f0 |= 1ull << j;
                }
                if (v1 && j > lane + 32) {
                    float ih = fmaxf(fminf(B1.z, bj.z) - fmaxf(B1.x, bj.x), 0.f);
                    float iw = fmaxf(fminf(B1.w, bj.w) - fmaxf(B1.y, bj.y), 0.f);
                    float inter = ih * iw;
                    if (inter > NMS_TH * fmaxf(a1 + aj - inter, 1e-8f)) f1 |= 1ull << j;
                }
            }

            // greedy: take best alive, keep it, kill whom it suppresses.
            ull alive = (cnt >= 64) ? ~0ull : ((1ull << cnt) - 1ull);
            ull kept  = 0;
            while (alive) {
                int i = __ffsll((long long)alive) - 1;
                kept |= 1ull << i;
                ull fi = __shfl_sync(FULL, (i >= 32) ? f1 : f0, i & 31);
                alive &= ~fi;
                alive &= ~(1ull << i);
            }

            // warp-aggregated append: ONE atomic per class-warp
            int total = __popcll(kept);
            int base  = 0;
            if (lane == 0 && total) base = atomicAdd(&g_nkept[b], total);
            base = __shfl_sync(FULL, base, 0);
            if (v0 && ((kept >> lane) & 1ull)) {
                int off = __popcll(kept & ((1ull << lane) - 1ull));
                if (base + off < KLCAP) g_klist[b * KLCAP + base + off] = k0;
            }
            if (v1 && ((kept >> (lane + 32)) & 1ull)) {
                int off = __popcll(kept & ((1ull << (lane + 32)) - 1ull));
                if (base + off < KLCAP) g_klist[b * KLCAP + base + off] = k1;
            }
            if (lane == 0) g_cnt[gw] = 0;   // restore zero-invariant

            // release: klist writes visible, then signal this batch
            __threadfence();
            __syncwarp();
            if (lane == 0) atomicAdd(&g_ndone[b], 1);
        }
    }

    __syncthreads();   // NMS warps done with sraw before reuse

    // ================= Phase B: redundant select (all 148 blocks) ===========
    {
        int*   hist = (int*)sraw;                // [2048]
        ull*   cand = (ull*)(sraw + 8192);       // [256]
        float* srow = (float*)(sraw + 10240);    // [600]
        int    b    = bid & 15;
        float* ob   = out + b * (MAXI * 6);

        for (int i = t; i < 2048; i += 1024) hist[i] = 0;
        for (int i = t; i < MAXI * 6; i += 1024) srow[i] = 0.0f;
        if (t == 0) { s_ncand = 0; s_bstar = 0; }

        // wait until this batch's 80 NMS tasks are done (single poller).
        // g_ndone/g_nkept reset by NEXT run's k_classify -> late redundant
        // pollers can never miss the signal.
        if (t == 0) {
            while (*(volatile int*)&g_ndone[b] < 80) { }
        }
        __syncthreads();
        __threadfence();   // acquire

        int mk = min(g_nkept[b], KLCAP);

        // coalesced key loads (mk ~ 960 expected; capacity 4096)
        ull myk[4];
#pragma unroll
        for (int u = 0; u < 4; u++) {
            int i = t + u * 1024;
            myk[u] = (i < mk) ? g_klist[b * KLCAP + i] : 0;
        }

        // histogram on score bits; kept => score in (0.7,1) -> bucket [819,2047]
#pragma unroll
        for (int u = 0; u < 4; u++) {
            if (myk[u]) {
                int bk = (int)(((unsigned)(myk[u] >> 32) - 0x3F000000u) >> 12);
                atomicAdd(&hist[min(2047, max(0, bk))], 1);
            }
        }
        __syncthreads();

        // two-level suffix scan: thread t covers buckets {2t, 2t+1};
        // find b* = max bucket with suffix count >= 100 (unique transition)
        {
            __shared__ int wsum[32];
            __shared__ int wsuf[32];
            int h0  = hist[2 * t];
            int h1  = hist[2 * t + 1];
            int loc = h0 + h1;
            int suf = loc;
            for (int d = 1; d < 32; d <<= 1) {
                int v = __shfl_down_sync(FULL, suf, d);
                if (lane + d < 32) suf += v;
            }
            if (lane == 0) wsum[w] = suf;
            __syncthreads();
            if (t == 0) {
                int acc = 0;
                for (int w2 = 31; w2 >= 0; w2--) { wsuf[w2] = acc; acc += wsum[w2]; }
            }
            __syncthreads();
            int run = wsuf[w] + (suf - loc);
            int S = run + h1;
            if (S >= MAXI && run < MAXI) s_bstar = 2 * t + 1;
            run = S;
            S = run + h0;
            if (S >= MAXI && run < MAXI) s_bstar = 2 * t;
        }
        __syncthreads();

        unsigned tbits = 0x3F000000u + ((unsigned)s_bstar << 12);
#pragma unroll
        for (int u = 0; u < 4; u++) {
            if (myk[u] && (unsigned)(myk[u] >> 32) >= tbits) {
                int p = atomicAdd(&s_ncand, 1);
                if (p < 256) cand[p] = myk[u];
            }
        }
        __syncthreads();

        // rank-based emit into shared staging: thread t handles candidate t;
        // rank = number of strictly greater keys (keys distinct via n bits).
        int m = min(s_ncand, 256);
        if (t < m) {
            ull my = cand[t];
            int rank = 0;
            for (int j = 0; j < m; j++) rank += (cand[j] > my);
            if (rank < MAXI) {
                int c0  = (int)((my >> 6) & 0x7Full);
                int pos = (int)(my & 63ull);
                float sc = __uint_as_float((unsigned)(my >> 32));
                float4 bx = g_sbox[(b * 80 + c0) * MAXC + pos];
                float* row = srow + rank * 6;
                row[0] = bx.x; row[1] = bx.y; row[2] = bx.z; row[3] = bx.w;
                row[4] = (float)(c0 + 1); row[5] = sc;
            }
        }
        __syncthreads();

        // every redundant block writes the IDENTICAL 600-float image
        for (int i = t; i < MAXI * 6; i += 1024) ob[i] = srow[i];
    }
}

// ---------------------------------------------------------------------------
extern "C" void kernel_launch(void* const* d_in, const int* in_sizes, int n_in,
                              void* d_out, int out_size) {
    const float* rois   = nullptr;
    const float* probs  = nullptr;
    const float* deltas = nullptr;
    for (int i = 0; i < n_in; i++) {
        if      (in_sizes[i] == BB * NN * 4)      rois   = (const float*)d_in[i];
        else if (in_sizes[i] == BB * NN * CC)     probs  = (const float*)d_in[i];
        else if (in_sizes[i] == BB * NN * CC * 4) deltas = (const float*)d_in[i];
    }
    float* out = (float*)d_out;

    k_classify<<<BB * NN / 4 / 8, 256>>>(rois, probs, deltas); // 4 ROIs/warp
    k_rest    <<<RGRID, 1024>>>(out);                          // NMS + select
}